// round 1
// baseline (speedup 1.0000x reference)
#include <cuda_runtime.h>
#include <cuda_bf16.h>
#include <cstdint>

// Problem dims
#define BB   32
#define TT   512
#define II   512
#define HH   1024
#define OO   512
#define MM   (BB*TT)        // 16384 rows of (b,t)

#define RNN_BLOCKS 128

// ---------------- scratch (static device globals; no allocation allowed) ----
__device__ float g_pre[MM * HH];          // 64 MB  : x@W_ih^T  (bias added later)
__device__ float g_partial[2 * 16 * BB * HH]; // 4 MB : double-buffered K-split partials
__device__ float g_logits[MM * OO];       // 32 MB : z@W_out^T + b_out
__device__ float g_zfallback[MM * HH];    // 64 MB : z if d_out has no z region

// ---------------- grid barrier (replay-safe, relative generation) -----------
__device__ unsigned g_bar_count = 0;
__device__ volatile unsigned g_bar_gen = 0;

__device__ __forceinline__ void grid_barrier() {
    __syncthreads();
    if (threadIdx.x == 0) {
        unsigned gen = g_bar_gen;          // read BEFORE arriving
        __threadfence();
        if (atomicAdd(&g_bar_count, 1) == RNN_BLOCKS - 1) {
            atomicExch(&g_bar_count, 0);
            __threadfence();
            g_bar_gen = gen + 1;
        } else {
            while (g_bar_gen == gen) { __nanosleep(64); }
        }
        __threadfence();
    }
    __syncthreads();
}

// ---------------- persistent Elman recurrence -------------------------------
// Grid: 128 blocks x 256 threads, all co-resident (<= 148 SMs, 41KB smem).
// Block (nc = bid&7, kc = bid>>3):
//   * holds W_hh[nc*128:(nc+1)*128, kc*64:(kc+1)*64] in SMEM for all 512 steps
//   * per step: self-reduce the 16 K-partials for h(t-1)[:, kc-slice] (+pre+bias,
//     tanh), GEMM vs its W slice, write its partial tile, one grid barrier.
//   * nc==0 blocks also emit z(t-1).
__global__ __launch_bounds__(256, 1)
void rnn_persistent(const float* __restrict__ pre,
                    const float* __restrict__ W_hh,
                    const float* __restrict__ b_ih,
                    const float* __restrict__ b_hh,
                    const float* __restrict__ h0,
                    float* __restrict__ z_out)
{
    __shared__ float Ws[64 * 128];   // [k][j] : W slice, j-contiguous rows
    __shared__ float h_s[64 * 33];   // [k][b] padded (33) -> conflict-free STS

    const int tid  = threadIdx.x;
    const int nc   = blockIdx.x & 7;
    const int kc   = blockIdx.x >> 3;
    const int lane = tid & 31;
    const int warp = tid >> 5;
    // micro-tile mapping: 32 j-groups (x4 j) , 8 b-groups (x4 b)
    const int jg = (lane & 7) + (warp & 3) * 8;   // 0..31
    const int bg = (lane >> 3) + (warp >> 2) * 4; // 0..7

    // Preload W slice transposed: Ws[k*128 + j] = W_hh[nc*128+j][kc*64+k]
    {
        const float* Wblk = W_hh + (size_t)(nc * 128) * HH + kc * 64;
        #pragma unroll
        for (int r = 0; r < 8; r++) {
            int i  = tid + r * 256;         // 0..2047
            int j  = i >> 4;                // 0..127
            int kq = (i & 15) * 4;          // 0..60
            float4 w = *(const float4*)(Wblk + (size_t)j * HH + kq);
            Ws[(kq + 0) * 128 + j] = w.x;
            Ws[(kq + 1) * 128 + j] = w.y;
            Ws[(kq + 2) * 128 + j] = w.z;
            Ws[(kq + 3) * 128 + j] = w.w;
        }
    }

    for (int t = 0; t < TT; t++) {
        // ---- materialize h(t-1)[:, kc*64 .. +64) into h_s[k][b] ----
        if (t == 0) {
            #pragma unroll
            for (int r = 0; r < 8; r++) {
                int e = tid + r * 256;       // 0..2047
                int b = e >> 6, k = e & 63;
                h_s[k * 33 + b] = h0[(size_t)b * HH + kc * 64 + k];
            }
        } else {
            const float* pbuf = g_partial + (size_t)((t - 1) & 1) * (16 * BB * HH);
            const int tt = t - 1;
            #pragma unroll
            for (int r = 0; r < 8; r++) {
                int e = tid + r * 256;
                int b = e >> 6, k = e & 63;
                int j = kc * 64 + k;
                float s = b_ih[j] + b_hh[j] + pre[((size_t)b * TT + tt) * HH + j];
                #pragma unroll
                for (int kk = 0; kk < 16; kk++)
                    s += pbuf[kk * (BB * HH) + b * HH + j];
                float hv = tanhf(s);
                h_s[k * 33 + b] = hv;
                if (nc == 0)
                    z_out[((size_t)b * TT + tt) * HH + j] = hv;
            }
        }
        __syncthreads();

        // ---- GEMM: partial[b][j] = sum_k h_s[k][b] * Ws[k][j] ----
        float acc[4][4];
        #pragma unroll
        for (int i = 0; i < 4; i++)
            #pragma unroll
            for (int q = 0; q < 4; q++) acc[i][q] = 0.f;

        #pragma unroll 16
        for (int k = 0; k < 64; k++) {
            float4 w4 = *(const float4*)&Ws[k * 128 + jg * 4];
            #pragma unroll
            for (int bb2 = 0; bb2 < 4; bb2++) {
                float hv = h_s[k * 33 + bg * 4 + bb2];
                acc[bb2][0] = fmaf(hv, w4.x, acc[bb2][0]);
                acc[bb2][1] = fmaf(hv, w4.y, acc[bb2][1]);
                acc[bb2][2] = fmaf(hv, w4.z, acc[bb2][2]);
                acc[bb2][3] = fmaf(hv, w4.w, acc[bb2][3]);
            }
        }

        // ---- write partial tile for step t ----
        float* pout = g_partial + (size_t)(t & 1) * (16 * BB * HH)
                      + (size_t)kc * (BB * HH) + nc * 128;
        #pragma unroll
        for (int bb2 = 0; bb2 < 4; bb2++) {
            float4 v = make_float4(acc[bb2][0], acc[bb2][1], acc[bb2][2], acc[bb2][3]);
            *(float4*)&pout[(size_t)(bg * 4 + bb2) * HH + jg * 4] = v;
        }
        __threadfence();
        grid_barrier();   // also provides the __syncthreads protecting h_s reuse
    }

    // ---- epilogue: z(T-1) ----
    if (nc == 0) {
        const float* pbuf = g_partial + (size_t)((TT - 1) & 1) * (16 * BB * HH);
        #pragma unroll
        for (int r = 0; r < 8; r++) {
            int e = tid + r * 256;
            int b = e >> 6, k = e & 63;
            int j = kc * 64 + k;
            float s = b_ih[j] + b_hh[j] + pre[((size_t)b * TT + (TT - 1)) * HH + j];
            #pragma unroll
            for (int kk = 0; kk < 16; kk++)
                s += pbuf[kk * (BB * HH) + b * HH + j];
            z_out[((size_t)b * TT + (TT - 1)) * HH + j] = tanhf(s);
        }
    }
}

// ---------------- SGEMM C[M,N] = A[M,K] * B[N,K]^T (+bias) ------------------
// 128x64 block tile, 16 K-tile, 256 threads, 8x4 micro-tile.
__global__ __launch_bounds__(256)
void sgemm_nt(int M, int N, int K,
              const float* __restrict__ A,
              const float* __restrict__ B,
              const float* __restrict__ bias,
              float* __restrict__ C)
{
    __shared__ float As[16][132];   // [k][m], padded (132*4B = 16B-aligned rows)
    __shared__ float Bs[16][68];    // [k][n], padded

    const int tid = threadIdx.x;
    const int m0  = blockIdx.x * 128;
    const int n0  = blockIdx.y * 64;
    const int tm  = tid >> 4;       // 0..15 -> 8 m each
    const int tn  = tid & 15;       // 0..15 -> 4 n each

    float acc[8][4];
    #pragma unroll
    for (int i = 0; i < 8; i++)
        #pragma unroll
        for (int j = 0; j < 4; j++) acc[i][j] = 0.f;

    for (int k0 = 0; k0 < K; k0 += 16) {
        #pragma unroll
        for (int r = 0; r < 2; r++) {
            int i  = tid + r * 256;     // 0..511  (128 m x 4 float4-k)
            int m  = i >> 2;
            int kq = (i & 3) * 4;
            float4 v = *(const float4*)&A[(size_t)(m0 + m) * K + k0 + kq];
            As[kq + 0][m] = v.x; As[kq + 1][m] = v.y;
            As[kq + 2][m] = v.z; As[kq + 3][m] = v.w;
        }
        {
            int n  = tid >> 2;          // 0..63
            int kq = (tid & 3) * 4;
            float4 v = *(const float4*)&B[(size_t)(n0 + n) * K + k0 + kq];
            Bs[kq + 0][n] = v.x; Bs[kq + 1][n] = v.y;
            Bs[kq + 2][n] = v.z; Bs[kq + 3][n] = v.w;
        }
        __syncthreads();

        #pragma unroll
        for (int k = 0; k < 16; k++) {
            float4 a0 = *(const float4*)&As[k][tm * 8];
            float4 a1 = *(const float4*)&As[k][tm * 8 + 4];
            float4 b0 = *(const float4*)&Bs[k][tn * 4];
            float av[8] = {a0.x, a0.y, a0.z, a0.w, a1.x, a1.y, a1.z, a1.w};
            float bv[4] = {b0.x, b0.y, b0.z, b0.w};
            #pragma unroll
            for (int i = 0; i < 8; i++)
                #pragma unroll
                for (int j = 0; j < 4; j++)
                    acc[i][j] = fmaf(av[i], bv[j], acc[i][j]);
        }
        __syncthreads();
    }

    float badd[4] = {0.f, 0.f, 0.f, 0.f};
    if (bias) {
        float4 bv4 = *(const float4*)&bias[n0 + tn * 4];
        badd[0] = bv4.x; badd[1] = bv4.y; badd[2] = bv4.z; badd[3] = bv4.w;
    }
    #pragma unroll
    for (int i = 0; i < 8; i++) {
        float4 v = make_float4(acc[i][0] + badd[0], acc[i][1] + badd[1],
                               acc[i][2] + badd[2], acc[i][3] + badd[3]);
        *(float4*)&C[(size_t)(m0 + tm * 8 + i) * N + n0 + tn * 4] = v;
    }
}

// ---------------- row softmax over 512 cols ---------------------------------
__global__ __launch_bounds__(256)
void softmax512(const float* __restrict__ logits, float* __restrict__ out)
{
    const int row = blockIdx.x;
    const int tid = threadIdx.x;
    const float* in = logits + (size_t)row * OO;
    float a = in[tid], b = in[tid + 256];

    float m = fmaxf(a, b);
    #pragma unroll
    for (int o = 16; o > 0; o >>= 1)
        m = fmaxf(m, __shfl_xor_sync(0xffffffffu, m, o));
    __shared__ float redm[8];
    __shared__ float reds[8];
    if ((tid & 31) == 0) redm[tid >> 5] = m;
    __syncthreads();
    float mm = redm[0];
    #pragma unroll
    for (int i = 1; i < 8; i++) mm = fmaxf(mm, redm[i]);

    float e0 = expf(a - mm), e1 = expf(b - mm);
    float s = e0 + e1;
    #pragma unroll
    for (int o = 16; o > 0; o >>= 1)
        s += __shfl_xor_sync(0xffffffffu, s, o);
    if ((tid & 31) == 0) reds[tid >> 5] = s;
    __syncthreads();
    float ss = 0.f;
    #pragma unroll
    for (int i = 0; i < 8; i++) ss += reds[i];
    float inv = 1.0f / ss;

    float* op = out + (size_t)row * OO;
    op[tid]       = e0 * inv;
    op[tid + 256] = e1 * inv;
}

// ---------------- launch -----------------------------------------------------
extern "C" void kernel_launch(void* const* d_in, const int* in_sizes, int n_in,
                              void* d_out, int out_size)
{
    const float* x     = (const float*)d_in[0];
    const float* h0    = (const float*)d_in[1];
    const float* W_ih  = (const float*)d_in[2];
    const float* W_hh  = (const float*)d_in[3];
    const float* b_ih  = (const float*)d_in[4];
    const float* b_hh  = (const float*)d_in[5];
    const float* W_out = (const float*)d_in[6];
    const float* b_out = (const float*)d_in[7];
    float* out = (float*)d_out;

    float *pre, *logits, *zfb;
    cudaGetSymbolAddress((void**)&pre,    g_pre);
    cudaGetSymbolAddress((void**)&logits, g_logits);
    cudaGetSymbolAddress((void**)&zfb,    g_zfallback);

    // Output tuple (out, z): softmax probs first, then z if the buffer has room.
    float* z = (out_size >= (int)((size_t)MM * (OO + HH)))
                 ? out + (size_t)MM * OO : zfb;

    // 1) pre = x @ W_ih^T   (bias folded into recurrence)
    dim3 g1(MM / 128, HH / 64);
    sgemm_nt<<<g1, 256>>>(MM, HH, II, x, W_ih, nullptr, pre);

    // 2) recurrence (persistent, writes z)
    rnn_persistent<<<RNN_BLOCKS, 256>>>(pre, W_hh, b_ih, b_hh, h0, z);

    // 3) logits = z @ W_out^T + b_out
    dim3 g3(MM / 128, OO / 64);
    sgemm_nt<<<g3, 256>>>(MM, OO, HH, z, W_out, b_out, logits);

    // 4) softmax rows -> out
    softmax512<<<MM, 256>>>(logits, out);
}

// round 2
// speedup vs baseline: 1.3232x; 1.3232x over previous
#include <cuda_runtime.h>
#include <cuda_bf16.h>
#include <cstdint>

// Problem dims
#define BB   32
#define TT   512
#define II   512
#define HH   1024
#define OO   512
#define MM   (BB*TT)

#define RNN_BLOCKS 128

// ---------------- scratch (static device globals) ---------------------------
__device__ float g_pre[MM * HH];            // x@W_ih^T + b_ih + b_hh
__device__ float g_partial[16 * BB * HH];   // K-split partials (single buffer)
__device__ float g_h[BB * HH];              // current hidden state
__device__ float g_logits[MM * OO];
__device__ float g_zfallback[MM * HH];

// ---------------- lean grid barrier -----------------------------------------
__device__ unsigned g_bar_count = 0;
__device__ unsigned g_bar_gen   = 0;

__device__ __forceinline__ void grid_barrier() {
    __syncthreads();
    if (threadIdx.x == 0) {
        unsigned* cnt = &g_bar_count;
        unsigned* gen = &g_bar_gen;
        unsigned g0;
        asm volatile("ld.acquire.gpu.u32 %0, [%1];" : "=r"(g0) : "l"(gen));
        unsigned prev;
        asm volatile("atom.add.release.gpu.u32 %0, [%1], 1;"
                     : "=r"(prev) : "l"(cnt));
        if (prev == RNN_BLOCKS - 1) {
            // all arrived: reset count, then release new generation
            asm volatile("st.relaxed.gpu.u32 [%0], 0;" :: "l"(cnt));
            unsigned g1 = g0 + 1;
            asm volatile("st.release.gpu.u32 [%0], %1;" :: "l"(gen), "r"(g1));
        } else {
            unsigned cur;
            do {
                asm volatile("ld.acquire.gpu.u32 %0, [%1];" : "=r"(cur) : "l"(gen));
            } while (cur == g0);
        }
    }
    __syncthreads();
}

// ---------------- persistent Elman recurrence (two-phase) --------------------
// 128 blocks x 256 threads. Block (nc = bid&7 -> 128-wide j chunk,
// kc = bid>>3 -> 64-wide k chunk) holds its W_hh slice in SMEM all 512 steps.
// Phase A: GEMM partial[b][nc-chunk] over its k-slice, write to g_partial[kc].
// Phase B: block reduces a disjoint 256-element share of h: sum 16 partials
//          + pre (biases pre-folded), tanh once, write g_h and z.
__global__ __launch_bounds__(256, 1)
void rnn_persistent(const float* __restrict__ pre,
                    const float* __restrict__ W_hh,
                    const float* __restrict__ h0,
                    float* __restrict__ z_out)
{
    __shared__ float Ws[64 * 128];   // [k][j]
    __shared__ float h_s[64 * 33];   // [k][b] padded

    const int tid  = threadIdx.x;
    const int nc   = blockIdx.x & 7;
    const int kc   = blockIdx.x >> 3;
    const int lane = tid & 31;
    const int warp = tid >> 5;
    const int jg = (lane & 7) + (warp & 3) * 8;   // 0..31
    const int bg = (lane >> 3) + (warp >> 2) * 4; // 0..7

    // Preload W slice transposed: Ws[k*128 + j] = W_hh[nc*128+j][kc*64+k]
    {
        const float* Wblk = W_hh + (size_t)(nc * 128) * HH + kc * 64;
        #pragma unroll
        for (int r = 0; r < 8; r++) {
            int i  = tid + r * 256;
            int j  = i >> 4;
            int kq = (i & 15) * 4;
            float4 w = *(const float4*)(Wblk + (size_t)j * HH + kq);
            Ws[(kq + 0) * 128 + j] = w.x;
            Ws[(kq + 1) * 128 + j] = w.y;
            Ws[(kq + 2) * 128 + j] = w.z;
            Ws[(kq + 3) * 128 + j] = w.w;
        }
    }

    // Phase-B element assignment: disjoint 256 elements per block
    const int eB = blockIdx.x * 256 + tid;        // 0..32767
    const int bB = eB >> 10;                      // batch
    const int jB = eB & 1023;                     // hidden idx

    for (int t = 0; t < TT; t++) {
        // ---- Phase A: load h(t-1) slice [k][b] into smem ----
        if (t == 0) {
            #pragma unroll
            for (int r = 0; r < 8; r++) {
                int e = tid + r * 256;
                int b = e >> 6, k = e & 63;
                h_s[k * 33 + b] = h0[(size_t)b * HH + kc * 64 + k];
            }
        } else {
            #pragma unroll
            for (int r = 0; r < 8; r++) {
                int e = tid + r * 256;
                int b = e >> 6, k = e & 63;
                h_s[k * 33 + b] = g_h[(size_t)b * HH + kc * 64 + k];
            }
        }
        __syncthreads();

        // ---- GEMM: partial[b][j] = sum_k h_s[k][b] * Ws[k][j] ----
        float acc[4][4];
        #pragma unroll
        for (int i = 0; i < 4; i++)
            #pragma unroll
            for (int q = 0; q < 4; q++) acc[i][q] = 0.f;

        #pragma unroll 16
        for (int k = 0; k < 64; k++) {
            float4 w4 = *(const float4*)&Ws[k * 128 + jg * 4];
            #pragma unroll
            for (int b2 = 0; b2 < 4; b2++) {
                float hv = h_s[k * 33 + bg * 4 + b2];
                acc[b2][0] = fmaf(hv, w4.x, acc[b2][0]);
                acc[b2][1] = fmaf(hv, w4.y, acc[b2][1]);
                acc[b2][2] = fmaf(hv, w4.z, acc[b2][2]);
                acc[b2][3] = fmaf(hv, w4.w, acc[b2][3]);
            }
        }

        float* pout = g_partial + (size_t)kc * (BB * HH) + nc * 128;
        #pragma unroll
        for (int b2 = 0; b2 < 4; b2++) {
            float4 v = make_float4(acc[b2][0], acc[b2][1], acc[b2][2], acc[b2][3]);
            *(float4*)&pout[(size_t)(bg * 4 + b2) * HH + jg * 4] = v;
        }
        grid_barrier();

        // ---- Phase B: reduce own share, tanh, publish h and z ----
        {
            float s = pre[((size_t)bB * TT + t) * HH + jB];
            #pragma unroll
            for (int kk = 0; kk < 16; kk++)
                s += g_partial[(size_t)kk * (BB * HH) + eB];
            float hv = tanhf(s);
            g_h[eB] = hv;
            z_out[((size_t)bB * TT + t) * HH + jB] = hv;
        }
        grid_barrier();
    }
}

// ---------------- SGEMM C[M,N] = A[M,K]*B[N,K]^T (+bias1+bias2) -------------
// 128x128 tile, BK=16, 256 threads, 8x8 micro-tile, double-buffered SMEM.
__global__ __launch_bounds__(256, 2)
void sgemm128(int M, int N, int K,
              const float* __restrict__ A,
              const float* __restrict__ B,
              const float* __restrict__ bias1,
              const float* __restrict__ bias2,
              float* __restrict__ C)
{
    __shared__ float As[2][16][132];
    __shared__ float Bs[2][16][132];

    const int tid = threadIdx.x;
    const int m0  = blockIdx.x * 128;
    const int n0  = blockIdx.y * 128;
    const int ty  = tid >> 4;      // 0..15 -> 8 rows
    const int tx  = tid & 15;      // 0..15 -> 8 cols

    // loader mapping: row = tid>>1 (0..127), kq = (tid&1)*8
    const int lr = tid >> 1;
    const int lk = (tid & 1) * 8;

    float acc[8][8];
    #pragma unroll
    for (int i = 0; i < 8; i++)
        #pragma unroll
        for (int j = 0; j < 8; j++) acc[i][j] = 0.f;

    const float* Aptr = A + (size_t)(m0 + lr) * K + lk;
    const float* Bptr = B + (size_t)(n0 + lr) * K + lk;

    // prologue: load tile 0
    {
        float4 a0 = *(const float4*)(Aptr);
        float4 a1 = *(const float4*)(Aptr + 4);
        float4 b0 = *(const float4*)(Bptr);
        float4 b1 = *(const float4*)(Bptr + 4);
        As[0][lk + 0][lr] = a0.x; As[0][lk + 1][lr] = a0.y;
        As[0][lk + 2][lr] = a0.z; As[0][lk + 3][lr] = a0.w;
        As[0][lk + 4][lr] = a1.x; As[0][lk + 5][lr] = a1.y;
        As[0][lk + 6][lr] = a1.z; As[0][lk + 7][lr] = a1.w;
        Bs[0][lk + 0][lr] = b0.x; Bs[0][lk + 1][lr] = b0.y;
        Bs[0][lk + 2][lr] = b0.z; Bs[0][lk + 3][lr] = b0.w;
        Bs[0][lk + 4][lr] = b1.x; Bs[0][lk + 5][lr] = b1.y;
        Bs[0][lk + 6][lr] = b1.z; Bs[0][lk + 7][lr] = b1.w;
    }
    __syncthreads();

    const int nTiles = K / 16;
    for (int kt = 0; kt < nTiles; kt++) {
        int cur = kt & 1, nxt = cur ^ 1;
        // prefetch next tile to registers
        float4 a0, a1, b0, b1;
        if (kt + 1 < nTiles) {
            const float* Ap = Aptr + (kt + 1) * 16;
            const float* Bp = Bptr + (kt + 1) * 16;
            a0 = *(const float4*)(Ap);
            a1 = *(const float4*)(Ap + 4);
            b0 = *(const float4*)(Bp);
            b1 = *(const float4*)(Bp + 4);
        }

        #pragma unroll
        for (int k = 0; k < 16; k++) {
            float4 av0 = *(const float4*)&As[cur][k][ty * 8];
            float4 av1 = *(const float4*)&As[cur][k][ty * 8 + 4];
            float4 bv0 = *(const float4*)&Bs[cur][k][tx * 8];
            float4 bv1 = *(const float4*)&Bs[cur][k][tx * 8 + 4];
            float av[8] = {av0.x, av0.y, av0.z, av0.w, av1.x, av1.y, av1.z, av1.w};
            float bv[8] = {bv0.x, bv0.y, bv0.z, bv0.w, bv1.x, bv1.y, bv1.z, bv1.w};
            #pragma unroll
            for (int i = 0; i < 8; i++)
                #pragma unroll
                for (int j = 0; j < 8; j++)
                    acc[i][j] = fmaf(av[i], bv[j], acc[i][j]);
        }

        if (kt + 1 < nTiles) {
            As[nxt][lk + 0][lr] = a0.x; As[nxt][lk + 1][lr] = a0.y;
            As[nxt][lk + 2][lr] = a0.z; As[nxt][lk + 3][lr] = a0.w;
            As[nxt][lk + 4][lr] = a1.x; As[nxt][lk + 5][lr] = a1.y;
            As[nxt][lk + 6][lr] = a1.z; As[nxt][lk + 7][lr] = a1.w;
            Bs[nxt][lk + 0][lr] = b0.x; Bs[nxt][lk + 1][lr] = b0.y;
            Bs[nxt][lk + 2][lr] = b0.z; Bs[nxt][lk + 3][lr] = b0.w;
            Bs[nxt][lk + 4][lr] = b1.x; Bs[nxt][lk + 5][lr] = b1.y;
            Bs[nxt][lk + 6][lr] = b1.z; Bs[nxt][lk + 7][lr] = b1.w;
            __syncthreads();
        }
    }

    float badd[8] = {0,0,0,0,0,0,0,0};
    if (bias1) {
        #pragma unroll
        for (int j = 0; j < 8; j++) badd[j] += bias1[n0 + tx * 8 + j];
    }
    if (bias2) {
        #pragma unroll
        for (int j = 0; j < 8; j++) badd[j] += bias2[n0 + tx * 8 + j];
    }
    #pragma unroll
    for (int i = 0; i < 8; i++) {
        float4 v0 = make_float4(acc[i][0] + badd[0], acc[i][1] + badd[1],
                                acc[i][2] + badd[2], acc[i][3] + badd[3]);
        float4 v1 = make_float4(acc[i][4] + badd[4], acc[i][5] + badd[5],
                                acc[i][6] + badd[6], acc[i][7] + badd[7]);
        float* crow = C + (size_t)(m0 + ty * 8 + i) * N + n0 + tx * 8;
        *(float4*)(crow)     = v0;
        *(float4*)(crow + 4) = v1;
    }
}

// ---------------- row softmax over 512 cols ---------------------------------
__global__ __launch_bounds__(256)
void softmax512(const float* __restrict__ logits, float* __restrict__ out)
{
    const int row = blockIdx.x;
    const int tid = threadIdx.x;
    const float* in = logits + (size_t)row * OO;
    float a = in[tid], b = in[tid + 256];

    float m = fmaxf(a, b);
    #pragma unroll
    for (int o = 16; o > 0; o >>= 1)
        m = fmaxf(m, __shfl_xor_sync(0xffffffffu, m, o));
    __shared__ float redm[8];
    __shared__ float reds[8];
    if ((tid & 31) == 0) redm[tid >> 5] = m;
    __syncthreads();
    float mm = redm[0];
    #pragma unroll
    for (int i = 1; i < 8; i++) mm = fmaxf(mm, redm[i]);

    float e0 = expf(a - mm), e1 = expf(b - mm);
    float s = e0 + e1;
    #pragma unroll
    for (int o = 16; o > 0; o >>= 1)
        s += __shfl_xor_sync(0xffffffffu, s, o);
    if ((tid & 31) == 0) reds[tid >> 5] = s;
    __syncthreads();
    float ss = 0.f;
    #pragma unroll
    for (int i = 0; i < 8; i++) ss += reds[i];
    float inv = 1.0f / ss;

    float* op = out + (size_t)row * OO;
    op[tid]       = e0 * inv;
    op[tid + 256] = e1 * inv;
}

// ---------------- launch -----------------------------------------------------
extern "C" void kernel_launch(void* const* d_in, const int* in_sizes, int n_in,
                              void* d_out, int out_size)
{
    const float* x     = (const float*)d_in[0];
    const float* h0    = (const float*)d_in[1];
    const float* W_ih  = (const float*)d_in[2];
    const float* W_hh  = (const float*)d_in[3];
    const float* b_ih  = (const float*)d_in[4];
    const float* b_hh  = (const float*)d_in[5];
    const float* W_out = (const float*)d_in[6];
    const float* b_out = (const float*)d_in[7];
    float* out = (float*)d_out;

    float *pre, *logits, *zfb;
    cudaGetSymbolAddress((void**)&pre,    g_pre);
    cudaGetSymbolAddress((void**)&logits, g_logits);
    cudaGetSymbolAddress((void**)&zfb,    g_zfallback);

    float* z = (out_size >= (int)((size_t)MM * (OO + HH)))
                 ? out + (size_t)MM * OO : zfb;

    // 1) pre = x @ W_ih^T + b_ih + b_hh   (both biases folded here)
    dim3 g1(MM / 128, HH / 128);
    sgemm128<<<g1, 256>>>(MM, HH, II, x, W_ih, b_ih, b_hh, pre);

    // 2) recurrence (persistent, two-phase, writes z)
    rnn_persistent<<<RNN_BLOCKS, 256>>>(pre, W_hh, h0, z);

    // 3) logits = z @ W_out^T + b_out
    dim3 g3(MM / 128, OO / 128);
    sgemm128<<<g3, 256>>>(MM, OO, HH, z, W_out, b_out, nullptr, logits);

    // 4) softmax rows -> out
    softmax512<<<MM, 256>>>(logits, out);
}

// round 4
// speedup vs baseline: 1.7429x; 1.3172x over previous
#include <cuda_runtime.h>
#include <cuda_bf16.h>
#include <cstdint>

// Problem dims
#define BB   32
#define TT   512
#define II   512
#define HH   1024
#define OO   512
#define MM   (BB*TT)

#define RNN_BLOCKS 128

// ---------------- scratch (static device globals) ---------------------------
__device__ float g_pre[MM * HH];
__device__ float g_partial[4 * BB * HH];
__device__ float g_logits[MM * OO];
__device__ float g_zfallback[MM * HH];

__device__ __nv_bfloat16 g_xhi[MM * II],    g_xlo[MM * II];
__device__ __nv_bfloat16 g_wih_hi[HH * II], g_wih_lo[HH * II];
__device__ __nv_bfloat16 g_wout_hi[OO * HH], g_wout_lo[OO * HH];
__device__ __nv_bfloat16 g_zhi[MM * HH],    g_zlo[MM * HH];
__device__ __nv_bfloat16 g_h0hi[BB * HH],   g_h0lo[BB * HH];

// ---------------- lean grid barrier -----------------------------------------
__device__ unsigned g_bar_count = 0;
__device__ unsigned g_bar_gen   = 0;

__device__ __forceinline__ void grid_barrier() {
    __syncthreads();
    if (threadIdx.x == 0) {
        unsigned* cnt = &g_bar_count;
        unsigned* gen = &g_bar_gen;
        unsigned g0;
        asm volatile("ld.acquire.gpu.u32 %0, [%1];" : "=r"(g0) : "l"(gen));
        unsigned prev;
        asm volatile("atom.add.release.gpu.u32 %0, [%1], 1;"
                     : "=r"(prev) : "l"(cnt));
        if (prev == RNN_BLOCKS - 1) {
            asm volatile("st.relaxed.gpu.u32 [%0], 0;" :: "l"(cnt));
            unsigned g1 = g0 + 1;
            asm volatile("st.release.gpu.u32 [%0], %1;" :: "l"(gen), "r"(g1));
        } else {
            unsigned cur;
            do {
                asm volatile("ld.acquire.gpu.u32 %0, [%1];" : "=r"(cur) : "l"(gen));
            } while (cur == g0);
        }
    }
    __syncthreads();
}

// ---------------- mma.sync helpers -------------------------------------------
__device__ __forceinline__ void mma16816(float& d0, float& d1, float& d2, float& d3,
                                         uint32_t a0, uint32_t a1, uint32_t a2, uint32_t a3,
                                         uint32_t b0, uint32_t b1)
{
    asm volatile(
        "mma.sync.aligned.m16n8k16.row.col.f32.bf16.bf16.f32 "
        "{%0,%1,%2,%3},{%4,%5,%6,%7},{%8,%9},{%0,%1,%2,%3};"
        : "+f"(d0), "+f"(d1), "+f"(d2), "+f"(d3)
        : "r"(a0), "r"(a1), "r"(a2), "r"(a3), "r"(b0), "r"(b1));
}

__device__ __forceinline__ uint32_t lds32(uint32_t a) {
    uint32_t v;
    asm volatile("ld.shared.b32 %0, [%1];" : "=r"(v) : "r"(a));
    return v;
}

__device__ __forceinline__ void cpa16(uint32_t s, const void* g) {
    asm volatile("cp.async.cg.shared.global [%0], [%1], 16;" :: "r"(s), "l"(g));
}

__device__ __forceinline__ uint32_t pack_hi2(float x, float y) {
    __nv_bfloat162 t;
    t.x = __float2bfloat16(x);
    t.y = __float2bfloat16(y);
    return *reinterpret_cast<uint32_t*>(&t);
}
__device__ __forceinline__ uint32_t pack_lo2(float x, float y) {
    __nv_bfloat16 hx = __float2bfloat16(x), hy = __float2bfloat16(y);
    __nv_bfloat162 t;
    t.x = __float2bfloat16(x - __bfloat162float(hx));
    t.y = __float2bfloat16(y - __bfloat162float(hy));
    return *reinterpret_cast<uint32_t*>(&t);
}

// ---------------- persistent Elman recurrence (mma phase A) ------------------
// 128 blocks = 32 j-chunks(32) x 4 k-splits(256). W_hh slice lives in
// REGISTERS (bf16 hi/lo fragments) for all 512 steps.
__global__ __launch_bounds__(256, 1)
void rnn_persistent(const float* __restrict__ pre,
                    const float* __restrict__ W_hh,
                    float* __restrict__ z_out)
{
    // h staging: [32 b][264 bf16] (stride 528B -> conflict-free frag LDS)
    __shared__ __align__(16) char h_hi[32 * 528];
    __shared__ __align__(16) char h_lo[32 * 528];

    const int tid  = threadIdx.x;
    const int wid  = tid >> 5;
    const int lane = tid & 31;
    const int grp  = lane >> 2;     // 0..7
    const int tig  = lane & 3;      // 0..3
    const int jc   = blockIdx.x >> 2;   // 0..31
    const int kc   = blockIdx.x & 3;    // 0..3
    const int mw   = wid & 1;       // b half (16)
    const int nw   = wid >> 1;      // j group (8)

    // ---- preload W fragments into registers (hi/lo), whole t-loop ----
    uint32_t whi0[16], whi1[16], wlo0[16], wlo1[16];
    {
        const int jrow = jc * 32 + nw * 8 + grp;
        const float* Wr = W_hh + (size_t)jrow * HH + kc * 256;
        #pragma unroll
        for (int ki = 0; ki < 16; ki++) {
            int k0 = ki * 16 + tig * 2;
            float w0 = Wr[k0],     w1 = Wr[k0 + 1];
            float w2 = Wr[k0 + 8], w3 = Wr[k0 + 9];
            whi0[ki] = pack_hi2(w0, w1);
            wlo0[ki] = pack_lo2(w0, w1);
            whi1[ki] = pack_hi2(w2, w3);
            wlo1[ki] = pack_lo2(w2, w3);
        }
    }

    const uint32_t shi = (uint32_t)__cvta_generic_to_shared(h_hi);
    const uint32_t slo = (uint32_t)__cvta_generic_to_shared(h_lo);

    // phase-B element assignment
    const int eB = blockIdx.x * 256 + tid;
    const int bB = eB >> 10;
    const int jB = eB & 1023;

    for (int t = 0; t < TT; t++) {
        // ---- stage h(t-1)[32 b][kc*256 .. +256) hi/lo into SMEM ----
        #pragma unroll
        for (int r = 0; r < 4; r++) {
            int idx = tid + r * 256;     // 0..1023
            int b   = idx >> 5;
            int c16 = idx & 31;
            size_t gof;
            if (t == 0) gof = (size_t)b * HH + kc * 256 + c16 * 8;
            else        gof = ((size_t)b * TT + (t - 1)) * HH + kc * 256 + c16 * 8;
            const __nv_bfloat16* sh = (t == 0) ? g_h0hi : g_zhi;
            const __nv_bfloat16* sl = (t == 0) ? g_h0lo : g_zlo;
            *(uint4*)(h_hi + b * 528 + c16 * 16) = *(const uint4*)(sh + gof);
            *(uint4*)(h_lo + b * 528 + c16 * 16) = *(const uint4*)(sl + gof);
        }
        __syncthreads();

        // ---- mma: C[16b x 8j] per warp, k=256 ----
        float c0 = 0.f, c1 = 0.f, c2 = 0.f, c3 = 0.f;
        const int rowA = mw * 16 + grp;
        #pragma unroll
        for (int ki = 0; ki < 16; ki++) {
            uint32_t base = rowA * 528 + ki * 32 + tig * 4;
            uint32_t ah0 = lds32(shi + base);
            uint32_t ah1 = lds32(shi + base + 8 * 528);
            uint32_t ah2 = lds32(shi + base + 16);
            uint32_t ah3 = lds32(shi + base + 8 * 528 + 16);
            uint32_t al0 = lds32(slo + base);
            uint32_t al1 = lds32(slo + base + 8 * 528);
            uint32_t al2 = lds32(slo + base + 16);
            uint32_t al3 = lds32(slo + base + 8 * 528 + 16);
            mma16816(c0, c1, c2, c3, ah0, ah1, ah2, ah3, whi0[ki], whi1[ki]);
            mma16816(c0, c1, c2, c3, ah0, ah1, ah2, ah3, wlo0[ki], wlo1[ki]);
            mma16816(c0, c1, c2, c3, al0, al1, al2, al3, whi0[ki], whi1[ki]);
        }

        // ---- write fp32 partial: [kc][b][jglobal] ----
        {
            int b0r = mw * 16 + grp;
            int jg  = jc * 32 + nw * 8 + tig * 2;
            float* p = g_partial + (size_t)kc * (BB * HH) + (size_t)b0r * HH + jg;
            *(float2*)p = make_float2(c0, c1);
            *(float2*)(p + 8 * HH) = make_float2(c2, c3);
        }

        // prefetch pre for phase B
        float pre_t = pre[((size_t)bB * TT + t) * HH + jB];

        grid_barrier();

        // ---- Phase B: reduce 4 partials, tanh, publish z fp32 + hi/lo ----
        {
            float s = pre_t;
            #pragma unroll
            for (int kk = 0; kk < 4; kk++)
                s += g_partial[(size_t)kk * (BB * HH) + eB];
            float hv = tanhf(s);
            size_t zidx = ((size_t)bB * TT + t) * HH + jB;
            z_out[zidx] = hv;
            __nv_bfloat16 zh = __float2bfloat16(hv);
            g_zhi[zidx] = zh;
            g_zlo[zidx] = __float2bfloat16(hv - __bfloat162float(zh));
        }
        grid_barrier();
    }
}

// ---------------- fp32 -> bf16 hi/lo split -----------------------------------
__global__ __launch_bounds__(256)
void split_bf16(const float* __restrict__ src,
                __nv_bfloat16* __restrict__ hi,
                __nv_bfloat16* __restrict__ lo, int n)
{
    int i = blockIdx.x * 256 + threadIdx.x;
    if (i < n) {
        float x = src[i];
        __nv_bfloat16 h = __float2bfloat16(x);
        hi[i] = h;
        lo[i] = __float2bfloat16(x - __bfloat162float(h));
    }
}

// ---------------- mma.sync bf16 3-split GEMM ---------------------------------
// C[M,N] = A[M,K]*B[N,K]^T (+bias1+bias2). 128x128 tile, BK=32, 256 threads,
// cp.async double-buffered SMEM. stride 40 bf16 (80B) per row.
#define GT_BYTES  (128 * 80)          // one tile (hi or lo) = 10240 B
#define GBUF      (4 * GT_BYTES)      // Ahi|Alo|Bhi|Blo     = 40960 B
#define GSMEM     (2 * GBUF)          // double buffer       = 81920 B

__global__ __launch_bounds__(256)
void bsgemm(int M, int N, int K,
            const __nv_bfloat16* __restrict__ Ahi, const __nv_bfloat16* __restrict__ Alo,
            const __nv_bfloat16* __restrict__ Bhi, const __nv_bfloat16* __restrict__ Blo,
            const float* __restrict__ bias1, const float* __restrict__ bias2,
            float* __restrict__ C)
{
    extern __shared__ __align__(16) char dsm[];
    const uint32_t sb = (uint32_t)__cvta_generic_to_shared(dsm);

    const int tid  = threadIdx.x;
    const int wid  = tid >> 5;
    const int lane = tid & 31;
    const int grp  = lane >> 2;
    const int tig  = lane & 3;
    const int wm   = wid & 1;      // 64-wide m half
    const int wn   = wid >> 1;     // 32-wide n quarter
    const int m0   = blockIdx.x * 128;
    const int n0   = blockIdx.y * 128;

    float acc[4][4][4];
    #pragma unroll
    for (int i = 0; i < 4; i++)
        #pragma unroll
        for (int j = 0; j < 4; j++)
            #pragma unroll
            for (int q = 0; q < 4; q++) acc[i][j][q] = 0.f;

    const int lrow = tid >> 2;     // 0..63? no: tid/4 -> 0..63  (two passes)
    const int lc16 = tid & 3;

    auto issue = [&](int kt, int buf) {
        #pragma unroll
        for (int r = 0; r < 2; r++) {
            int row = lrow + r * 64;
            uint32_t so = (uint32_t)buf * GBUF + row * 80 + lc16 * 16;
            size_t goA = (size_t)(m0 + row) * K + kt * 32 + lc16 * 8;
            size_t goB = (size_t)(n0 + row) * K + kt * 32 + lc16 * 8;
            cpa16(sb + so,                Ahi + goA);
            cpa16(sb + so + GT_BYTES,     Alo + goA);
            cpa16(sb + so + 2 * GT_BYTES, Bhi + goB);
            cpa16(sb + so + 3 * GT_BYTES, Blo + goB);
        }
        asm volatile("cp.async.commit_group;" ::: "memory");
    };

    const int KT = K >> 5;
    issue(0, 0);

    for (int kt = 0; kt < KT; kt++) {
        if (kt + 1 < KT) {
            issue(kt + 1, (kt + 1) & 1);
            asm volatile("cp.async.wait_group 1;" ::: "memory");
        } else {
            asm volatile("cp.async.wait_group 0;" ::: "memory");
        }
        __syncthreads();

        const uint32_t bufo = (uint32_t)(kt & 1) * GBUF;
        #pragma unroll
        for (int h16 = 0; h16 < 2; h16++) {
            uint32_t ah[4][4], al[4][4];
            #pragma unroll
            for (int mi = 0; mi < 4; mi++) {
                int row = wm * 64 + mi * 16 + grp;
                uint32_t base = sb + bufo + row * 80 + h16 * 32 + tig * 4;
                ah[mi][0] = lds32(base);
                ah[mi][1] = lds32(base + 8 * 80);
                ah[mi][2] = lds32(base + 16);
                ah[mi][3] = lds32(base + 8 * 80 + 16);
                al[mi][0] = lds32(base + GT_BYTES);
                al[mi][1] = lds32(base + GT_BYTES + 8 * 80);
                al[mi][2] = lds32(base + GT_BYTES + 16);
                al[mi][3] = lds32(base + GT_BYTES + 8 * 80 + 16);
            }
            uint32_t bh[4][2], bl[4][2];
            #pragma unroll
            for (int ni = 0; ni < 4; ni++) {
                int row = wn * 32 + ni * 8 + grp;
                uint32_t base = sb + bufo + 2 * GT_BYTES + row * 80 + h16 * 32 + tig * 4;
                bh[ni][0] = lds32(base);
                bh[ni][1] = lds32(base + 16);
                bl[ni][0] = lds32(base + GT_BYTES);
                bl[ni][1] = lds32(base + GT_BYTES + 16);
            }
            #pragma unroll
            for (int mi = 0; mi < 4; mi++)
                #pragma unroll
                for (int ni = 0; ni < 4; ni++) {
                    float* a = acc[mi][ni];
                    mma16816(a[0], a[1], a[2], a[3],
                             ah[mi][0], ah[mi][1], ah[mi][2], ah[mi][3],
                             bh[ni][0], bh[ni][1]);
                    mma16816(a[0], a[1], a[2], a[3],
                             ah[mi][0], ah[mi][1], ah[mi][2], ah[mi][3],
                             bl[ni][0], bl[ni][1]);
                    mma16816(a[0], a[1], a[2], a[3],
                             al[mi][0], al[mi][1], al[mi][2], al[mi][3],
                             bh[ni][0], bh[ni][1]);
                }
        }
        __syncthreads();
    }

    // epilogue
    #pragma unroll
    for (int ni = 0; ni < 4; ni++) {
        int gc = n0 + wn * 32 + ni * 8 + tig * 2;
        float bs0 = 0.f, bs1 = 0.f;
        if (bias1) { bs0 += bias1[gc]; bs1 += bias1[gc + 1]; }
        if (bias2) { bs0 += bias2[gc]; bs1 += bias2[gc + 1]; }
        #pragma unroll
        for (int mi = 0; mi < 4; mi++) {
            int gr = m0 + wm * 64 + mi * 16 + grp;
            float* a = acc[mi][ni];
            *(float2*)&C[(size_t)gr * N + gc] = make_float2(a[0] + bs0, a[1] + bs1);
            *(float2*)&C[(size_t)(gr + 8) * N + gc] = make_float2(a[2] + bs0, a[3] + bs1);
        }
    }
}

// ---------------- row softmax over 512 cols ---------------------------------
__global__ __launch_bounds__(256)
void softmax512(const float* __restrict__ logits, float* __restrict__ out)
{
    const int row = blockIdx.x;
    const int tid = threadIdx.x;
    const float* in = logits + (size_t)row * OO;
    float a = in[tid], b = in[tid + 256];

    float m = fmaxf(a, b);
    #pragma unroll
    for (int o = 16; o > 0; o >>= 1)
        m = fmaxf(m, __shfl_xor_sync(0xffffffffu, m, o));
    __shared__ float redm[8];
    __shared__ float reds[8];
    if ((tid & 31) == 0) redm[tid >> 5] = m;
    __syncthreads();
    float mm = redm[0];
    #pragma unroll
    for (int i = 1; i < 8; i++) mm = fmaxf(mm, redm[i]);

    float e0 = expf(a - mm), e1 = expf(b - mm);
    float s = e0 + e1;
    #pragma unroll
    for (int o = 16; o > 0; o >>= 1)
        s += __shfl_xor_sync(0xffffffffu, s, o);
    if ((tid & 31) == 0) reds[tid >> 5] = s;
    __syncthreads();
    float ss = 0.f;
    #pragma unroll
    for (int i = 0; i < 8; i++) ss += reds[i];
    float inv = 1.0f / ss;

    float* op = out + (size_t)row * OO;
    op[tid]       = e0 * inv;
    op[tid + 256] = e1 * inv;
}

// ---------------- launch -----------------------------------------------------
extern "C" void kernel_launch(void* const* d_in, const int* in_sizes, int n_in,
                              void* d_out, int out_size)
{
    const float* x     = (const float*)d_in[0];
    const float* h0    = (const float*)d_in[1];
    const float* W_ih  = (const float*)d_in[2];
    const float* W_hh  = (const float*)d_in[3];
    const float* b_ih  = (const float*)d_in[4];
    const float* b_hh  = (const float*)d_in[5];
    const float* W_out = (const float*)d_in[6];
    const float* b_out = (const float*)d_in[7];
    float* out = (float*)d_out;

    float *pre, *logits, *zfb;
    cudaGetSymbolAddress((void**)&pre,    g_pre);
    cudaGetSymbolAddress((void**)&logits, g_logits);
    cudaGetSymbolAddress((void**)&zfb,    g_zfallback);
    __nv_bfloat16 *xhi, *xlo, *wih_hi, *wih_lo, *wout_hi, *wout_lo, *zhi, *zlo, *h0hi, *h0lo;
    cudaGetSymbolAddress((void**)&xhi, g_xhi);
    cudaGetSymbolAddress((void**)&xlo, g_xlo);
    cudaGetSymbolAddress((void**)&wih_hi, g_wih_hi);
    cudaGetSymbolAddress((void**)&wih_lo, g_wih_lo);
    cudaGetSymbolAddress((void**)&wout_hi, g_wout_hi);
    cudaGetSymbolAddress((void**)&wout_lo, g_wout_lo);
    cudaGetSymbolAddress((void**)&zhi, g_zhi);
    cudaGetSymbolAddress((void**)&zlo, g_zlo);
    cudaGetSymbolAddress((void**)&h0hi, g_h0hi);
    cudaGetSymbolAddress((void**)&h0lo, g_h0lo);

    cudaFuncSetAttribute(bsgemm, cudaFuncAttributeMaxDynamicSharedMemorySize, GSMEM);

    float* z = (out_size >= (int)((size_t)MM * (OO + HH)))
                 ? out + (size_t)MM * OO : zfb;

    // 0) bf16 hi/lo splits
    split_bf16<<<(MM * II + 255) / 256, 256>>>(x, xhi, xlo, MM * II);
    split_bf16<<<(HH * II + 255) / 256, 256>>>(W_ih, wih_hi, wih_lo, HH * II);
    split_bf16<<<(OO * HH + 255) / 256, 256>>>(W_out, wout_hi, wout_lo, OO * HH);
    split_bf16<<<(BB * HH + 255) / 256, 256>>>(h0, h0hi, h0lo, BB * HH);

    // 1) pre = x @ W_ih^T + b_ih + b_hh
    dim3 g1(MM / 128, HH / 128);
    bsgemm<<<g1, 256, GSMEM>>>(MM, HH, II, xhi, xlo, wih_hi, wih_lo, b_ih, b_hh, pre);

    // 2) recurrence (persistent; emits z fp32 + bf16 hi/lo)
    rnn_persistent<<<RNN_BLOCKS, 256>>>(pre, W_hh, z);

    // 3) logits = z @ W_out^T + b_out
    dim3 g3(MM / 128, OO / 128);
    bsgemm<<<g3, 256, GSMEM>>>(MM, OO, HH, zhi, zlo, wout_hi, wout_lo, b_out, nullptr, logits);

    // 4) softmax rows -> out
    softmax512<<<MM, 256>>>(logits, out);
}

// round 5
// speedup vs baseline: 1.9616x; 1.1255x over previous
#include <cuda_runtime.h>
#include <cuda_bf16.h>
#include <cstdint>

// Problem dims
#define BB   32
#define TT   512
#define II   512
#define HH   1024
#define OO   512
#define MM   (BB*TT)

#define BAR_BLOCKS 64

// ---------------- scratch (static device globals) ---------------------------
__device__ float g_pre[MM * HH];
__device__ float g_logits[MM * OO];
__device__ float g_zfallback[MM * HH];

__device__ __nv_bfloat16 g_xhi[MM * II],    g_xlo[MM * II];
__device__ __nv_bfloat16 g_wih_hi[HH * II], g_wih_lo[HH * II];
__device__ __nv_bfloat16 g_wout_hi[OO * HH], g_wout_lo[OO * HH];
__device__ __nv_bfloat16 g_zhi[MM * HH],    g_zlo[MM * HH];
__device__ __nv_bfloat16 g_h0hi[BB * HH],   g_h0lo[BB * HH];

// ---------------- lean grid barrier -----------------------------------------
__device__ unsigned g_bar_count = 0;
__device__ unsigned g_bar_gen   = 0;

__device__ __forceinline__ void grid_barrier() {
    __syncthreads();
    if (threadIdx.x == 0) {
        unsigned* cnt = &g_bar_count;
        unsigned* gen = &g_bar_gen;
        unsigned g0;
        asm volatile("ld.acquire.gpu.u32 %0, [%1];" : "=r"(g0) : "l"(gen));
        unsigned prev;
        asm volatile("atom.add.release.gpu.u32 %0, [%1], 1;"
                     : "=r"(prev) : "l"(cnt));
        if (prev == BAR_BLOCKS - 1) {
            asm volatile("st.relaxed.gpu.u32 [%0], 0;" :: "l"(cnt));
            unsigned g1 = g0 + 1;
            asm volatile("st.release.gpu.u32 [%0], %1;" :: "l"(gen), "r"(g1));
        } else {
            unsigned cur;
            do {
                asm volatile("ld.acquire.gpu.u32 %0, [%1];" : "=r"(cur) : "l"(gen));
            } while (cur == g0);
        }
    }
    __syncthreads();
}

// ---------------- mma.sync helpers -------------------------------------------
__device__ __forceinline__ void mma16816(float& d0, float& d1, float& d2, float& d3,
                                         uint32_t a0, uint32_t a1, uint32_t a2, uint32_t a3,
                                         uint32_t b0, uint32_t b1)
{
    asm volatile(
        "mma.sync.aligned.m16n8k16.row.col.f32.bf16.bf16.f32 "
        "{%0,%1,%2,%3},{%4,%5,%6,%7},{%8,%9},{%0,%1,%2,%3};"
        : "+f"(d0), "+f"(d1), "+f"(d2), "+f"(d3)
        : "r"(a0), "r"(a1), "r"(a2), "r"(a3), "r"(b0), "r"(b1));
}

__device__ __forceinline__ void ldsm4(uint32_t& r0, uint32_t& r1, uint32_t& r2, uint32_t& r3,
                                      uint32_t addr)
{
    asm volatile("ldmatrix.sync.aligned.m8n8.x4.shared.b16 {%0,%1,%2,%3}, [%4];"
                 : "=r"(r0), "=r"(r1), "=r"(r2), "=r"(r3) : "r"(addr));
}

__device__ __forceinline__ uint32_t lds32(uint32_t a) {
    uint32_t v;
    asm volatile("ld.shared.b32 %0, [%1];" : "=r"(v) : "r"(a));
    return v;
}

__device__ __forceinline__ void cpa16(uint32_t s, const void* g) {
    asm volatile("cp.async.cg.shared.global [%0], [%1], 16;" :: "r"(s), "l"(g));
}

__device__ __forceinline__ uint32_t pack_hi2(float x, float y) {
    __nv_bfloat162 t;
    t.x = __float2bfloat16(x);
    t.y = __float2bfloat16(y);
    return *reinterpret_cast<uint32_t*>(&t);
}
__device__ __forceinline__ uint32_t pack_lo2(float x, float y) {
    __nv_bfloat16 hx = __float2bfloat16(x), hy = __float2bfloat16(y);
    __nv_bfloat162 t;
    t.x = __float2bfloat16(x - __bfloat162float(hx));
    t.y = __float2bfloat16(y - __bfloat162float(hy));
    return *reinterpret_cast<uint32_t*>(&t);
}

// ---------------- persistent Elman recurrence --------------------------------
// 64 blocks x 256 threads, 1 block/SM. Block jc owns j in [jc*16, jc*16+16),
// computes FULL k=1024 (k split 4-way across warps, reduced in SMEM).
// W_hh slice lives in registers all 512 steps. ONE grid barrier per step.
// SMEM: h_hi[32 x 2064B] | h_lo[32 x 2064B] | psum[4][32][16] f32
#define HROW   2064
#define SM_HHI 0
#define SM_HLO (32 * HROW)
#define SM_PS  (64 * HROW)
#define RNN_SMEM (SM_PS + 4 * 32 * 16 * 4)

__global__ __launch_bounds__(256, 1)
void rnn_persistent(const float* __restrict__ pre,
                    const float* __restrict__ W_hh,
                    float* __restrict__ z_out)
{
    extern __shared__ __align__(16) char dsm[];
    const uint32_t sb = (uint32_t)__cvta_generic_to_shared(dsm);

    const int tid  = threadIdx.x;
    const int wid  = tid >> 5;
    const int lane = tid & 31;
    const int grp  = lane >> 2;       // 0..7
    const int tig  = lane & 3;        // 0..3
    const int jc   = blockIdx.x;      // 0..63
    const int kw   = wid & 3;         // k quarter (256)
    const int mw   = wid >> 2;        // b half (16)

    // ---- preload W fragments (hi/lo) into registers, whole t-loop ----
    // nt in {0,1}: j-subtile of 8. Frag: b0=(j grp, k tig*2..+1), b1=(k+8..+9)
    uint32_t whi0[2][16], whi1[2][16], wlo0[2][16], wlo1[2][16];
    #pragma unroll
    for (int nt = 0; nt < 2; nt++) {
        const int jrow = jc * 16 + nt * 8 + grp;
        const float* Wr = W_hh + (size_t)jrow * HH + kw * 256;
        #pragma unroll
        for (int ki = 0; ki < 16; ki++) {
            int k0 = ki * 16 + tig * 2;
            float w0 = Wr[k0],     w1 = Wr[k0 + 1];
            float w2 = Wr[k0 + 8], w3 = Wr[k0 + 9];
            whi0[nt][ki] = pack_hi2(w0, w1);
            wlo0[nt][ki] = pack_lo2(w0, w1);
            whi1[nt][ki] = pack_hi2(w2, w3);
            wlo1[nt][ki] = pack_lo2(w2, w3);
        }
    }

    // ldmatrix.x4 per-lane address component (A frag m16k16):
    // row = mw*16 + (lane&7) + ((lane>>3)&1)*8 ; colByte = (lane>>4)*16
    const uint32_t lrow = mw * 16 + (lane & 7) + ((lane >> 3) & 1) * 8;
    const uint32_t lcol = ((uint32_t)lane >> 4) * 16;
    const uint32_t aoff = lrow * HROW + (uint32_t)kw * 512 + lcol;

    // phase-B element pair
    const int e0 = tid * 2;             // 0..510
    const int bB = e0 >> 4;             // 0..31
    const int jB = e0 & 15;             // even
    const int jglob = jc * 16 + jB;

    float* const psum = (float*)(dsm + SM_PS);

    for (int t = 0; t < TT; t++) {
        // prefetch pre for phase B (independent of h)
        float2 pre2 = *(const float2*)&pre[((size_t)bB * TT + t) * HH + jglob];

        // ---- stage full h(t-1) hi then lo via cp.async (2 groups) ----
        const __nv_bfloat16* sh = (t == 0) ? g_h0hi : g_zhi;
        const __nv_bfloat16* sl = (t == 0) ? g_h0lo : g_zlo;
        const int tprev = (t == 0) ? 0 : (t - 1);
        #pragma unroll
        for (int r = 0; r < 16; r++) {
            int idx = tid + r * 256;        // 0..4095
            int b   = idx >> 7;
            int c   = idx & 127;            // 16B chunk
            size_t gof = (t == 0) ? ((size_t)b * HH + c * 8)
                                  : (((size_t)b * TT + tprev) * HH + c * 8);
            cpa16(sb + SM_HHI + b * HROW + c * 16, sh + gof);
        }
        asm volatile("cp.async.commit_group;" ::: "memory");
        #pragma unroll
        for (int r = 0; r < 16; r++) {
            int idx = tid + r * 256;
            int b   = idx >> 7;
            int c   = idx & 127;
            size_t gof = (t == 0) ? ((size_t)b * HH + c * 8)
                                  : (((size_t)b * TT + tprev) * HH + c * 8);
            cpa16(sb + SM_HLO + b * HROW + c * 16, sl + gof);
        }
        asm volatile("cp.async.commit_group;" ::: "memory");

        asm volatile("cp.async.wait_group 1;" ::: "memory");
        __syncthreads();

        // ---- terms 1+2: h_hi x (W_hi + W_lo)  [h_lo still in flight] ----
        float a1[2][4] = {{0,0,0,0},{0,0,0,0}};
        float a2[2][4] = {{0,0,0,0},{0,0,0,0}};
        #pragma unroll
        for (int ki = 0; ki < 16; ki++) {
            uint32_t ah0, ah1, ah2, ah3;
            ldsm4(ah0, ah1, ah2, ah3, sb + SM_HHI + aoff + ki * 32);
            #pragma unroll
            for (int nt = 0; nt < 2; nt++) {
                mma16816(a1[nt][0], a1[nt][1], a1[nt][2], a1[nt][3],
                         ah0, ah1, ah2, ah3, whi0[nt][ki], whi1[nt][ki]);
                mma16816(a2[nt][0], a2[nt][1], a2[nt][2], a2[nt][3],
                         ah0, ah1, ah2, ah3, wlo0[nt][ki], wlo1[nt][ki]);
            }
        }

        asm volatile("cp.async.wait_group 0;" ::: "memory");
        __syncthreads();

        // ---- term 3: h_lo x W_hi ----
        float a3[2][4] = {{0,0,0,0},{0,0,0,0}};
        #pragma unroll
        for (int ki = 0; ki < 16; ki++) {
            uint32_t al0, al1, al2, al3;
            ldsm4(al0, al1, al2, al3, sb + SM_HLO + aoff + ki * 32);
            #pragma unroll
            for (int nt = 0; nt < 2; nt++) {
                mma16816(a3[nt][0], a3[nt][1], a3[nt][2], a3[nt][3],
                         al0, al1, al2, al3, whi0[nt][ki], whi1[nt][ki]);
            }
        }

        // ---- write per-warp k-partials to SMEM ----
        #pragma unroll
        for (int nt = 0; nt < 2; nt++) {
            int b0r = mw * 16 + grp;
            int jj  = nt * 8 + tig * 2;
            float c0 = a1[nt][0] + a2[nt][0] + a3[nt][0];
            float c1 = a1[nt][1] + a2[nt][1] + a3[nt][1];
            float c2 = a1[nt][2] + a2[nt][2] + a3[nt][2];
            float c3 = a1[nt][3] + a2[nt][3] + a3[nt][3];
            *(float2*)&psum[(size_t)kw * 512 + b0r * 16 + jj]       = make_float2(c0, c1);
            *(float2*)&psum[(size_t)kw * 512 + (b0r + 8) * 16 + jj] = make_float2(c2, c3);
        }
        __syncthreads();

        // ---- phase B: reduce 4 k-partials, tanh, publish z (fp32+hi/lo) ----
        {
            float s0 = pre2.x, s1 = pre2.y;
            #pragma unroll
            for (int kk = 0; kk < 4; kk++) {
                float2 p = *(float2*)&psum[kk * 512 + bB * 16 + jB];
                s0 += p.x; s1 += p.y;
            }
            float h0v = tanhf(s0);
            float h1v = tanhf(s1);
            size_t zidx = ((size_t)bB * TT + t) * HH + jglob;
            *(float2*)&z_out[zidx] = make_float2(h0v, h1v);
            *(uint32_t*)&g_zhi[zidx] = pack_hi2(h0v, h1v);
            *(uint32_t*)&g_zlo[zidx] = pack_lo2(h0v, h1v);
        }

        grid_barrier();
    }
}

// ---------------- fp32 -> bf16 hi/lo split -----------------------------------
__global__ __launch_bounds__(256)
void split_bf16(const float* __restrict__ src,
                __nv_bfloat16* __restrict__ hi,
                __nv_bfloat16* __restrict__ lo, int n)
{
    int i = blockIdx.x * 256 + threadIdx.x;
    if (i < n) {
        float x = src[i];
        __nv_bfloat16 h = __float2bfloat16(x);
        hi[i] = h;
        lo[i] = __float2bfloat16(x - __bfloat162float(h));
    }
}

// ---------------- mma.sync bf16 3-split GEMM ---------------------------------
#define GT_BYTES  (128 * 80)
#define GBUF      (4 * GT_BYTES)
#define GSMEM     (2 * GBUF)

__global__ __launch_bounds__(256)
void bsgemm(int M, int N, int K,
            const __nv_bfloat16* __restrict__ Ahi, const __nv_bfloat16* __restrict__ Alo,
            const __nv_bfloat16* __restrict__ Bhi, const __nv_bfloat16* __restrict__ Blo,
            const float* __restrict__ bias1, const float* __restrict__ bias2,
            float* __restrict__ C)
{
    extern __shared__ __align__(16) char dsm[];
    const uint32_t sb = (uint32_t)__cvta_generic_to_shared(dsm);

    const int tid  = threadIdx.x;
    const int wid  = tid >> 5;
    const int lane = tid & 31;
    const int grp  = lane >> 2;
    const int tig  = lane & 3;
    const int wm   = wid & 1;
    const int wn   = wid >> 1;
    const int m0   = blockIdx.x * 128;
    const int n0   = blockIdx.y * 128;

    float acc[4][4][4];
    #pragma unroll
    for (int i = 0; i < 4; i++)
        #pragma unroll
        for (int j = 0; j < 4; j++)
            #pragma unroll
            for (int q = 0; q < 4; q++) acc[i][j][q] = 0.f;

    const int lrow = tid >> 2;
    const int lc16 = tid & 3;

    auto issue = [&](int kt, int buf) {
        #pragma unroll
        for (int r = 0; r < 2; r++) {
            int row = lrow + r * 64;
            uint32_t so = (uint32_t)buf * GBUF + row * 80 + lc16 * 16;
            size_t goA = (size_t)(m0 + row) * K + kt * 32 + lc16 * 8;
            size_t goB = (size_t)(n0 + row) * K + kt * 32 + lc16 * 8;
            cpa16(sb + so,                Ahi + goA);
            cpa16(sb + so + GT_BYTES,     Alo + goA);
            cpa16(sb + so + 2 * GT_BYTES, Bhi + goB);
            cpa16(sb + so + 3 * GT_BYTES, Blo + goB);
        }
        asm volatile("cp.async.commit_group;" ::: "memory");
    };

    const int KT = K >> 5;
    issue(0, 0);

    for (int kt = 0; kt < KT; kt++) {
        if (kt + 1 < KT) {
            issue(kt + 1, (kt + 1) & 1);
            asm volatile("cp.async.wait_group 1;" ::: "memory");
        } else {
            asm volatile("cp.async.wait_group 0;" ::: "memory");
        }
        __syncthreads();

        const uint32_t bufo = (uint32_t)(kt & 1) * GBUF;
        #pragma unroll
        for (int h16 = 0; h16 < 2; h16++) {
            uint32_t ah[4][4], al[4][4];
            #pragma unroll
            for (int mi = 0; mi < 4; mi++) {
                int row = wm * 64 + mi * 16 + grp;
                uint32_t base = sb + bufo + row * 80 + h16 * 32 + tig * 4;
                ah[mi][0] = lds32(base);
                ah[mi][1] = lds32(base + 8 * 80);
                ah[mi][2] = lds32(base + 16);
                ah[mi][3] = lds32(base + 8 * 80 + 16);
                al[mi][0] = lds32(base + GT_BYTES);
                al[mi][1] = lds32(base + GT_BYTES + 8 * 80);
                al[mi][2] = lds32(base + GT_BYTES + 16);
                al[mi][3] = lds32(base + GT_BYTES + 8 * 80 + 16);
            }
            uint32_t bh[4][2], bl[4][2];
            #pragma unroll
            for (int ni = 0; ni < 4; ni++) {
                int row = wn * 32 + ni * 8 + grp;
                uint32_t base = sb + bufo + 2 * GT_BYTES + row * 80 + h16 * 32 + tig * 4;
                bh[ni][0] = lds32(base);
                bh[ni][1] = lds32(base + 16);
                bl[ni][0] = lds32(base + GT_BYTES);
                bl[ni][1] = lds32(base + GT_BYTES + 16);
            }
            #pragma unroll
            for (int mi = 0; mi < 4; mi++)
                #pragma unroll
                for (int ni = 0; ni < 4; ni++) {
                    float* a = acc[mi][ni];
                    mma16816(a[0], a[1], a[2], a[3],
                             ah[mi][0], ah[mi][1], ah[mi][2], ah[mi][3],
                             bh[ni][0], bh[ni][1]);
                    mma16816(a[0], a[1], a[2], a[3],
                             ah[mi][0], ah[mi][1], ah[mi][2], ah[mi][3],
                             bl[ni][0], bl[ni][1]);
                    mma16816(a[0], a[1], a[2], a[3],
                             al[mi][0], al[mi][1], al[mi][2], al[mi][3],
                             bh[ni][0], bh[ni][1]);
                }
        }
        __syncthreads();
    }

    #pragma unroll
    for (int ni = 0; ni < 4; ni++) {
        int gc = n0 + wn * 32 + ni * 8 + tig * 2;
        float bs0 = 0.f, bs1 = 0.f;
        if (bias1) { bs0 += bias1[gc]; bs1 += bias1[gc + 1]; }
        if (bias2) { bs0 += bias2[gc]; bs1 += bias2[gc + 1]; }
        #pragma unroll
        for (int mi = 0; mi < 4; mi++) {
            int gr = m0 + wm * 64 + mi * 16 + grp;
            float* a = acc[mi][ni];
            *(float2*)&C[(size_t)gr * N + gc] = make_float2(a[0] + bs0, a[1] + bs1);
            *(float2*)&C[(size_t)(gr + 8) * N + gc] = make_float2(a[2] + bs0, a[3] + bs1);
        }
    }
}

// ---------------- row softmax over 512 cols ---------------------------------
__global__ __launch_bounds__(256)
void softmax512(const float* __restrict__ logits, float* __restrict__ out)
{
    const int row = blockIdx.x;
    const int tid = threadIdx.x;
    const float* in = logits + (size_t)row * OO;
    float a = in[tid], b = in[tid + 256];

    float m = fmaxf(a, b);
    #pragma unroll
    for (int o = 16; o > 0; o >>= 1)
        m = fmaxf(m, __shfl_xor_sync(0xffffffffu, m, o));
    __shared__ float redm[8];
    __shared__ float reds[8];
    if ((tid & 31) == 0) redm[tid >> 5] = m;
    __syncthreads();
    float mm = redm[0];
    #pragma unroll
    for (int i = 1; i < 8; i++) mm = fmaxf(mm, redm[i]);

    float e0 = expf(a - mm), e1 = expf(b - mm);
    float s = e0 + e1;
    #pragma unroll
    for (int o = 16; o > 0; o >>= 1)
        s += __shfl_xor_sync(0xffffffffu, s, o);
    if ((tid & 31) == 0) reds[tid >> 5] = s;
    __syncthreads();
    float ss = 0.f;
    #pragma unroll
    for (int i = 0; i < 8; i++) ss += reds[i];
    float inv = 1.0f / ss;

    float* op = out + (size_t)row * OO;
    op[tid]       = e0 * inv;
    op[tid + 256] = e1 * inv;
}

// ---------------- launch -----------------------------------------------------
extern "C" void kernel_launch(void* const* d_in, const int* in_sizes, int n_in,
                              void* d_out, int out_size)
{
    const float* x     = (const float*)d_in[0];
    const float* h0    = (const float*)d_in[1];
    const float* W_ih  = (const float*)d_in[2];
    const float* W_hh  = (const float*)d_in[3];
    const float* b_ih  = (const float*)d_in[4];
    const float* b_hh  = (const float*)d_in[5];
    const float* W_out = (const float*)d_in[6];
    const float* b_out = (const float*)d_in[7];
    float* out = (float*)d_out;

    float *pre, *logits, *zfb;
    cudaGetSymbolAddress((void**)&pre,    g_pre);
    cudaGetSymbolAddress((void**)&logits, g_logits);
    cudaGetSymbolAddress((void**)&zfb,    g_zfallback);
    __nv_bfloat16 *xhi, *xlo, *wih_hi, *wih_lo, *wout_hi, *wout_lo, *zhi, *zlo, *h0hi, *h0lo;
    cudaGetSymbolAddress((void**)&xhi, g_xhi);
    cudaGetSymbolAddress((void**)&xlo, g_xlo);
    cudaGetSymbolAddress((void**)&wih_hi, g_wih_hi);
    cudaGetSymbolAddress((void**)&wih_lo, g_wih_lo);
    cudaGetSymbolAddress((void**)&wout_hi, g_wout_hi);
    cudaGetSymbolAddress((void**)&wout_lo, g_wout_lo);
    cudaGetSymbolAddress((void**)&zhi, g_zhi);
    cudaGetSymbolAddress((void**)&zlo, g_zlo);
    cudaGetSymbolAddress((void**)&h0hi, g_h0hi);
    cudaGetSymbolAddress((void**)&h0lo, g_h0lo);

    cudaFuncSetAttribute(bsgemm, cudaFuncAttributeMaxDynamicSharedMemorySize, GSMEM);
    cudaFuncSetAttribute(rnn_persistent, cudaFuncAttributeMaxDynamicSharedMemorySize, RNN_SMEM);

    float* z = (out_size >= (int)((size_t)MM * (OO + HH)))
                 ? out + (size_t)MM * OO : zfb;

    // 0) bf16 hi/lo splits
    split_bf16<<<(MM * II + 255) / 256, 256>>>(x, xhi, xlo, MM * II);
    split_bf16<<<(HH * II + 255) / 256, 256>>>(W_ih, wih_hi, wih_lo, HH * II);
    split_bf16<<<(OO * HH + 255) / 256, 256>>>(W_out, wout_hi, wout_lo, OO * HH);
    split_bf16<<<(BB * HH + 255) / 256, 256>>>(h0, h0hi, h0lo, BB * HH);

    // 1) pre = x @ W_ih^T + b_ih + b_hh
    dim3 g1(MM / 128, HH / 128);
    bsgemm<<<g1, 256, GSMEM>>>(MM, HH, II, xhi, xlo, wih_hi, wih_lo, b_ih, b_hh, pre);

    // 2) recurrence (persistent, 64 blocks, 1 barrier/step)
    rnn_persistent<<<BAR_BLOCKS, 256, RNN_SMEM>>>(pre, W_hh, z);

    // 3) logits = z @ W_out^T + b_out
    dim3 g3(MM / 128, OO / 128);
    bsgemm<<<g3, 256, GSMEM>>>(MM, OO, HH, zhi, zlo, wout_hi, wout_lo, b_out, nullptr, logits);

    // 4) softmax rows -> out
    softmax512<<<MM, 256>>>(logits, out);
}